// round 1
// baseline (speedup 1.0000x reference)
#include <cuda_runtime.h>

#define N_ROWS 200000
#define HID    512
#define HHALF  256
#define NG     2000
#define TM     64
#define KC     32

// Pre-transposed W1: g_W1T[k][c] = W1[c][k]
__device__ float g_W1T[HID * HHALF];

// ---------------- small helpers ----------------

__device__ __forceinline__ unsigned long long splat2(float x) {
    unsigned long long r;
    unsigned int xi = __float_as_uint(x);
    asm("mov.b64 %0, {%1, %1};" : "=l"(r) : "r"(xi));
    return r;
}

__device__ __forceinline__ float2 u2f(unsigned long long v) {
    float2 f;
    asm("mov.b64 {%0, %1}, %2;" : "=f"(f.x), "=f"(f.y) : "l"(v));
    return f;
}

#define FFMA2(d, a, b) asm("fma.rn.f32x2 %0, %1, %2, %0;" : "+l"(d) : "l"(a), "l"(b))

__device__ __forceinline__ float silu_f(float z) {
    return z * (1.0f / (1.0f + __expf(-z)));
}

// ---------------- kernels ----------------

__global__ void zero_out_kernel(float* out) {
    int i = blockIdx.x * blockDim.x + threadIdx.x;
    if (i < NG) out[i] = 0.0f;
}

__global__ void transpose_w1_kernel(const float* __restrict__ W1) {
    int idx = blockIdx.x * blockDim.x + threadIdx.x;  // coalesced read of W1[c][k]
    if (idx < HID * HHALF) {
        int c = idx >> 9;       // / 512
        int k = idx & (HID - 1);
        g_W1T[k * HHALF + c] = W1[idx];
    }
}

__global__ __launch_bounds__(256, 2) void fused_kernel(
    const float* __restrict__ h,
    const void*  __restrict__ batch_raw,
    const float* __restrict__ b1,
    const float* __restrict__ W2,
    const float* __restrict__ b2,
    const float* __restrict__ Ww,
    const float* __restrict__ bw,
    float* __restrict__ out)
{
    // 48 KB static smem total
    __shared__ unsigned long long hs2[KC][TM];   // pre-splatted h chunk (k-major)  16 KB
    __shared__ float ws[KC][HHALF];              // W1T chunk                       32 KB

    const int tid = threadIdx.x;
    const int ci  = tid & 31;   // col-group: cols [ci*8, ci*8+8)
    const int ri  = tid >> 5;   // row-group: rows [ri*8, ri*8+8)
    const int row0 = blockIdx.x * TM;

    // dtype detection for batch: sorted array, last int32-word is 0 iff data is int64
    // (word 199999 is the high half of element 99999 for int64; a nonzero value for int32)
    const bool is64 = (((const int*)batch_raw)[N_ROWS - 1] == 0);

    unsigned long long acc[8][4];
    #pragma unroll
    for (int r = 0; r < 8; ++r)
        #pragma unroll
        for (int p = 0; p < 4; ++p) acc[r][p] = 0ull;

    float aacc[8];
    #pragma unroll
    for (int j = 0; j < 8; ++j) aacc[j] = 0.0f;

    for (int chunk = 0; chunk < HID / KC; ++chunk) {
        const int k0 = chunk * KC;
        __syncthreads();

        // --- stage W1T chunk: [KC][256] floats, fully coalesced float4 copy ---
        {
            const float4* src = reinterpret_cast<const float4*>(g_W1T + k0 * HHALF);
            float4* dst = reinterpret_cast<float4*>(&ws[0][0]);
            #pragma unroll
            for (int i = 0; i < 8; ++i) dst[tid + i * 256] = src[tid + i * 256];
        }
        // --- stage h chunk transposed + pre-splatted: hs2[kk][row] = {h,h} ---
        {
            #pragma unroll
            for (int j = 0; j < 2; ++j) {
                int s   = tid + j * 256;    // 0..511 over (row, k-quad)
                int row = s >> 3;           // 64 rows
                int kq  = s & 7;            // 8 float4 per row chunk
                float4 v = *reinterpret_cast<const float4*>(
                    h + (size_t)(row0 + row) * HID + k0 + kq * 4);
                hs2[kq * 4 + 0][row] = splat2(v.x);
                hs2[kq * 4 + 1][row] = splat2(v.y);
                hs2[kq * 4 + 2][row] = splat2(v.z);
                hs2[kq * 4 + 3][row] = splat2(v.w);
            }
        }
        __syncthreads();

        // --- fused alpha GEMV partial: lane ci handles k = k0+ci for this warp's 8 rows ---
        {
            float wwk = __ldg(Ww + k0 + ci);
            #pragma unroll
            for (int j = 0; j < 8; ++j) {
                float hv = __uint_as_float((unsigned int)hs2[ci][ri * 8 + j]);
                aacc[j] = fmaf(hv, wwk, aacc[j]);
            }
        }

        // --- main GEMM microkernel: 8 rows x 8 cols per thread, f32x2 packed ---
        #pragma unroll 8
        for (int kk = 0; kk < KC; ++kk) {
            ulonglong2 h01 = *reinterpret_cast<const ulonglong2*>(&hs2[kk][ri * 8 + 0]);
            ulonglong2 h23 = *reinterpret_cast<const ulonglong2*>(&hs2[kk][ri * 8 + 2]);
            ulonglong2 h45 = *reinterpret_cast<const ulonglong2*>(&hs2[kk][ri * 8 + 4]);
            ulonglong2 h67 = *reinterpret_cast<const ulonglong2*>(&hs2[kk][ri * 8 + 6]);
            ulonglong2 w01 = *reinterpret_cast<const ulonglong2*>(&ws[kk][ci * 8 + 0]);
            ulonglong2 w23 = *reinterpret_cast<const ulonglong2*>(&ws[kk][ci * 8 + 4]);

            FFMA2(acc[0][0], h01.x, w01.x); FFMA2(acc[0][1], h01.x, w01.y);
            FFMA2(acc[0][2], h01.x, w23.x); FFMA2(acc[0][3], h01.x, w23.y);
            FFMA2(acc[1][0], h01.y, w01.x); FFMA2(acc[1][1], h01.y, w01.y);
            FFMA2(acc[1][2], h01.y, w23.x); FFMA2(acc[1][3], h01.y, w23.y);
            FFMA2(acc[2][0], h23.x, w01.x); FFMA2(acc[2][1], h23.x, w01.y);
            FFMA2(acc[2][2], h23.x, w23.x); FFMA2(acc[2][3], h23.x, w23.y);
            FFMA2(acc[3][0], h23.y, w01.x); FFMA2(acc[3][1], h23.y, w01.y);
            FFMA2(acc[3][2], h23.y, w23.x); FFMA2(acc[3][3], h23.y, w23.y);
            FFMA2(acc[4][0], h45.x, w01.x); FFMA2(acc[4][1], h45.x, w01.y);
            FFMA2(acc[4][2], h45.x, w23.x); FFMA2(acc[4][3], h45.x, w23.y);
            FFMA2(acc[5][0], h45.y, w01.x); FFMA2(acc[5][1], h45.y, w01.y);
            FFMA2(acc[5][2], h45.y, w23.x); FFMA2(acc[5][3], h45.y, w23.y);
            FFMA2(acc[6][0], h67.x, w01.x); FFMA2(acc[6][1], h67.x, w01.y);
            FFMA2(acc[6][2], h67.x, w23.x); FFMA2(acc[6][3], h67.x, w23.y);
            FFMA2(acc[7][0], h67.y, w01.x); FFMA2(acc[7][1], h67.y, w01.y);
            FFMA2(acc[7][2], h67.y, w23.x); FFMA2(acc[7][3], h67.y, w23.y);
        }
    }

    // ---- epilogue: bias + silu + W2 contraction over this thread's 8 cols ----
    const float b2v = __ldg(b2);
    const float bwv = __ldg(bw);
    float4 b1a = *reinterpret_cast<const float4*>(b1 + ci * 8);
    float4 b1b = *reinterpret_cast<const float4*>(b1 + ci * 8 + 4);
    float4 w2a = *reinterpret_cast<const float4*>(W2 + ci * 8);
    float4 w2b = *reinterpret_cast<const float4*>(W2 + ci * 8 + 4);

    float part[8];
    #pragma unroll
    for (int r = 0; r < 8; ++r) {
        float2 a0 = u2f(acc[r][0]);
        float2 a1 = u2f(acc[r][1]);
        float2 a2 = u2f(acc[r][2]);
        float2 a3 = u2f(acc[r][3]);
        float p = 0.0f;
        p += silu_f(a0.x + b1a.x) * w2a.x;
        p += silu_f(a0.y + b1a.y) * w2a.y;
        p += silu_f(a1.x + b1a.z) * w2a.z;
        p += silu_f(a1.y + b1a.w) * w2a.w;
        p += silu_f(a2.x + b1b.x) * w2b.x;
        p += silu_f(a2.y + b1b.y) * w2b.y;
        p += silu_f(a3.x + b1b.z) * w2b.z;
        p += silu_f(a3.y + b1b.w) * w2b.w;
        part[r] = p;
    }

    // warp = 32 col-threads of the same row-group -> butterfly reduce over cols
    #pragma unroll
    for (int r = 0; r < 8; ++r)
        #pragma unroll
        for (int o = 16; o; o >>= 1)
            part[r] += __shfl_xor_sync(0xffffffffu, part[r], o);
    #pragma unroll
    for (int j = 0; j < 8; ++j)
        #pragma unroll
        for (int o = 16; o; o >>= 1)
            aacc[j] += __shfl_xor_sync(0xffffffffu, aacc[j], o);

    if (ci < 8) {
        int row = row0 + ri * 8 + ci;
        int g;
        if (is64) g = (int)((const long long*)batch_raw)[row];
        else      g = ((const int*)batch_raw)[row];
        float v = (part[ci] + b2v) * (aacc[ci] + bwv);
        atomicAdd(out + g, v);
    }
}

// ---------------- launch ----------------

extern "C" void kernel_launch(void* const* d_in, const int* in_sizes, int n_in,
                              void* d_out, int out_size) {
    const float* h     = (const float*)d_in[0];
    // d_in[1] edge_index, d_in[2] edge_weight, d_in[4] alpha: unused by reference math
    const void*  batch = d_in[3];
    const float* W1    = (const float*)d_in[5];
    const float* b1    = (const float*)d_in[6];
    const float* W2    = (const float*)d_in[7];
    const float* b2    = (const float*)d_in[8];
    const float* Ww    = (const float*)d_in[9];
    const float* bw    = (const float*)d_in[10];
    float* out = (float*)d_out;

    zero_out_kernel<<<(NG + 255) / 256, 256>>>(out);
    transpose_w1_kernel<<<(HID * HHALF) / 256, 256>>>(W1);
    fused_kernel<<<N_ROWS / TM, 256>>>(h, batch, b1, W2, b2, Ww, bw, out);
}

// round 3
// speedup vs baseline: 3.4446x; 3.4446x over previous
#include <cuda_runtime.h>
#include <cuda_bf16.h>
#include <cstdint>

#define N_ROWS 200000
#define HID    512
#define HHALF  256
#define NG     2000
#define MROWS  128
#define KC     32
#define NCHUNK 16
#define NTHREADS 512

// smem layout (bytes)
#define OFF_WW     0
#define OFF_B1     2048
#define OFF_W2     3072
#define OFF_ALPHA  4096
#define OFF_ROWSUM 4608
#define OFF_A      5120
#define OFF_B      46080
#define SMEM_TOTAL 128000
#define ASTR   80        // padded row stride (32 bf16 -> 80B) : conflict-free ldmatrix
#define A_HL   10240     // 128 rows * 80
#define A_STG  20480
#define B_HL   20480     // 256 rows * 80
#define B_STG  40960

__device__ __nv_bfloat16 g_W1hi[HHALF * HID];
__device__ __nv_bfloat16 g_W1lo[HHALF * HID];

// ---------------- helpers ----------------
__device__ __forceinline__ uint32_t smem_u32(const void* p) {
    uint32_t a;
    asm("{ .reg .u64 t; cvta.to.shared.u64 t, %1; cvt.u32.u64 %0, t; }" : "=r"(a) : "l"(p));
    return a;
}
#define LDSM4(r, a) asm volatile("ldmatrix.sync.aligned.m8n8.x4.shared.b16 {%0,%1,%2,%3}, [%4];" \
    : "=r"((r)[0]),"=r"((r)[1]),"=r"((r)[2]),"=r"((r)[3]) : "r"(a))
#define LDSM2(r, a) asm volatile("ldmatrix.sync.aligned.m8n8.x2.shared.b16 {%0,%1}, [%2];" \
    : "=r"((r)[0]),"=r"((r)[1]) : "r"(a))
#define MMA16816(d, a, b) asm volatile( \
    "mma.sync.aligned.m16n8k16.row.col.f32.bf16.bf16.f32 " \
    "{%0,%1,%2,%3}, {%4,%5,%6,%7}, {%8,%9}, {%0,%1,%2,%3};" \
    : "+f"((d)[0]),"+f"((d)[1]),"+f"((d)[2]),"+f"((d)[3]) \
    : "r"((a)[0]),"r"((a)[1]),"r"((a)[2]),"r"((a)[3]), "r"((b)[0]),"r"((b)[1]))
#define CPASYNC16(dst, src) asm volatile("cp.async.cg.shared.global [%0], [%1], 16;" :: "r"(dst), "l"(src) : "memory")
#define CPCOMMIT() asm volatile("cp.async.commit_group;" ::: "memory")
#define CPWAIT0()  asm volatile("cp.async.wait_group 0;" ::: "memory")

__device__ __forceinline__ uint32_t pack_bf16x2(float e_lo, float e_hi) {
    uint32_t r;
    asm("cvt.rn.bf16x2.f32 %0, %1, %2;" : "=r"(r) : "f"(e_hi), "f"(e_lo));
    return r;
}
__device__ __forceinline__ float bflo_f(uint32_t p) { return __uint_as_float(p << 16); }
__device__ __forceinline__ float bfhi_f(uint32_t p) { return __uint_as_float(p & 0xffff0000u); }
__device__ __forceinline__ float silu_f(float z) { return __fdividef(z, 1.0f + __expf(-z)); }

// ---------------- prep kernels ----------------
__global__ void zero_out_kernel(float* out) {
    int i = blockIdx.x * blockDim.x + threadIdx.x;
    if (i < NG) out[i] = 0.0f;
}
__global__ void convert_w1_kernel(const float* __restrict__ W1) {
    int i = blockIdx.x * blockDim.x + threadIdx.x;
    float x = W1[i];
    __nv_bfloat16 hi = __float2bfloat16(x);
    g_W1hi[i] = hi;
    g_W1lo[i] = __float2bfloat16(x - __bfloat162float(hi));
}

// ---------------- main kernel ----------------
__global__ __launch_bounds__(NTHREADS, 1)
void fused_mma_kernel(
    const float* __restrict__ h,
    const void*  __restrict__ batch_raw,
    const float* __restrict__ b1,
    const float* __restrict__ W2,
    const float* __restrict__ b2,
    const float* __restrict__ Ww,
    const float* __restrict__ bw,
    float* __restrict__ out)
{
    extern __shared__ char smem[];
    const uint32_t sbase = smem_u32(smem);
    const int tid = threadIdx.x;
    const int wid = tid >> 5, lid = tid & 31;
    const int row0 = blockIdx.x * MROWS;

    float* wws  = (float*)(smem + OFF_WW);
    float* b1s  = (float*)(smem + OFF_B1);
    float* w2s  = (float*)(smem + OFF_W2);
    float* alps = (float*)(smem + OFF_ALPHA);
    float* rsum = (float*)(smem + OFF_ROWSUM);

    if (tid < 256) { b1s[tid] = b1[tid]; w2s[tid] = W2[tid]; }
    if (tid < 128) { ((float4*)wws)[tid] = ((const float4*)Ww)[tid]; rsum[tid] = 0.0f; }

    const bool is64 = (((const int*)batch_raw)[N_ROWS - 1] == 0);

    // A staging mapping: thread -> (row, float4-quad)
    const int arow = tid >> 2;                 // 0..127
    const int akq  = tid & 3;                  // quads akq and akq+4
    const bool rvalid = (row0 + arow) < N_ROWS;
    const float* hrow = h + (size_t)(row0 + arow) * HID;

    float acc[4][4][4];
    #pragma unroll
    for (int a = 0; a < 4; ++a)
        #pragma unroll
        for (int b = 0; b < 4; ++b)
            #pragma unroll
            for (int c = 0; c < 4; ++c) acc[a][b][c] = 0.0f;

    float aacc = 0.0f;
    float4 v0, v1;

    // ---------------- prologue: stage chunk 0 into stage 0 ----------------
    #pragma unroll
    for (int j = 0; j < 4; ++j) {
        int task = tid + j * 512;
        int hl = task >> 10, rem = task & 1023;
        int n = rem >> 2, unit = rem & 3;
        const __nv_bfloat16* src = (hl ? g_W1lo : g_W1hi) + n * HID + unit * 8;
        uint32_t dst = sbase + OFF_B + hl * B_HL + n * ASTR + unit * 16;
        CPASYNC16(dst, src);
    }
    CPCOMMIT();
    if (rvalid) {
        v0 = *(const float4*)(hrow + akq * 4);
        v1 = *(const float4*)(hrow + akq * 4 + 16);
    } else { v0 = make_float4(0,0,0,0); v1 = v0; }
    __syncthreads();   // consts staged

    // convert & store A chunk 0 (stage 0) + alpha partial
    {
        float4 w0 = ((const float4*)wws)[akq];
        float4 w1 = ((const float4*)wws)[akq + 4];
        aacc = fmaf(v0.x,w0.x, fmaf(v0.y,w0.y, fmaf(v0.z,w0.z, fmaf(v0.w,w0.w, aacc))));
        aacc = fmaf(v1.x,w1.x, fmaf(v1.y,w1.y, fmaf(v1.z,w1.z, fmaf(v1.w,w1.w, aacc))));
        uint32_t h01 = pack_bf16x2(v0.x, v0.y), h23 = pack_bf16x2(v0.z, v0.w);
        uint32_t g01 = pack_bf16x2(v1.x, v1.y), g23 = pack_bf16x2(v1.z, v1.w);
        uint32_t l01 = pack_bf16x2(v0.x - bflo_f(h01), v0.y - bfhi_f(h01));
        uint32_t l23 = pack_bf16x2(v0.z - bflo_f(h23), v0.w - bfhi_f(h23));
        uint32_t m01 = pack_bf16x2(v1.x - bflo_f(g01), v1.y - bfhi_f(g01));
        uint32_t m23 = pack_bf16x2(v1.z - bflo_f(g23), v1.w - bfhi_f(g23));
        char* ab = smem + OFF_A + arow * ASTR + akq * 8;
        *(uint2*)(ab)             = make_uint2(h01, h23);
        *(uint2*)(ab + 32)        = make_uint2(g01, g23);
        *(uint2*)(ab + A_HL)      = make_uint2(l01, l23);
        *(uint2*)(ab + A_HL + 32) = make_uint2(m01, m23);
    }
    CPWAIT0();
    __syncthreads();

    const int wm = wid >> 3, wn = wid & 7;
    const uint32_t a_off = (uint32_t)(wm * 64 + (lid & 15)) * ASTR + (lid >> 4) * 16;
    const uint32_t b_off = (uint32_t)(wn * 32 + (lid & 7)) * ASTR + ((lid >> 3) & 1) * 16;

    // ---------------- main loop ----------------
    for (int c = 0; c < NCHUNK; ++c) {
        const int s = c & 1;
        const int k1 = (c + 1) * KC;
        const bool more = (c + 1 < NCHUNK);

        if (more) {
            #pragma unroll
            for (int j = 0; j < 4; ++j) {
                int task = tid + j * 512;
                int hl = task >> 10, rem = task & 1023;
                int n = rem >> 2, unit = rem & 3;
                const __nv_bfloat16* src = (hl ? g_W1lo : g_W1hi) + n * HID + k1 + unit * 8;
                uint32_t dst = sbase + OFF_B + (s ^ 1) * B_STG + hl * B_HL + n * ASTR + unit * 16;
                CPASYNC16(dst, src);
            }
            CPCOMMIT();
            if (rvalid) {
                v0 = *(const float4*)(hrow + k1 + akq * 4);
                v1 = *(const float4*)(hrow + k1 + akq * 4 + 16);
            } else { v0 = make_float4(0,0,0,0); v1 = v0; }
        }

        // ---- MMA on stage s: (Ahi*Bhi + Ahi*Blo + Alo*Bhi) ----
        {
            const uint32_t abase = sbase + OFF_A + s * A_STG;
            const uint32_t bbase = sbase + OFF_B + s * B_STG;
            #pragma unroll
            for (int ks = 0; ks < 2; ++ks) {
                const uint32_t ko = ks * 32;
                uint32_t af[4][4], bh[4][2], bl[4][2];
                #pragma unroll
                for (int mt = 0; mt < 4; ++mt) LDSM4(af[mt], abase + a_off + mt * (16 * ASTR) + ko);
                #pragma unroll
                for (int nt = 0; nt < 4; ++nt) LDSM2(bh[nt], bbase + b_off + nt * (8 * ASTR) + ko);
                #pragma unroll
                for (int mt = 0; mt < 4; ++mt)
                    #pragma unroll
                    for (int nt = 0; nt < 4; ++nt) MMA16816(acc[mt][nt], af[mt], bh[nt]);
                #pragma unroll
                for (int nt = 0; nt < 4; ++nt) LDSM2(bl[nt], bbase + B_HL + b_off + nt * (8 * ASTR) + ko);
                #pragma unroll
                for (int mt = 0; mt < 4; ++mt)
                    #pragma unroll
                    for (int nt = 0; nt < 4; ++nt) MMA16816(acc[mt][nt], af[mt], bl[nt]);
                #pragma unroll
                for (int mt = 0; mt < 4; ++mt) LDSM4(af[mt], abase + A_HL + a_off + mt * (16 * ASTR) + ko);
                #pragma unroll
                for (int mt = 0; mt < 4; ++mt)
                    #pragma unroll
                    for (int nt = 0; nt < 4; ++nt) MMA16816(acc[mt][nt], af[mt], bh[nt]);
            }
        }

        if (more) {
            // convert & store A chunk c+1 into stage s^1 + alpha partial
            float4 w0 = ((const float4*)wws)[(k1 >> 2) + akq];
            float4 w1 = ((const float4*)wws)[(k1 >> 2) + akq + 4];
            aacc = fmaf(v0.x,w0.x, fmaf(v0.y,w0.y, fmaf(v0.z,w0.z, fmaf(v0.w,w0.w, aacc))));
            aacc = fmaf(v1.x,w1.x, fmaf(v1.y,w1.y, fmaf(v1.z,w1.z, fmaf(v1.w,w1.w, aacc))));
            uint32_t h01 = pack_bf16x2(v0.x, v0.y), h23 = pack_bf16x2(v0.z, v0.w);
            uint32_t g01 = pack_bf16x2(v1.x, v1.y), g23 = pack_bf16x2(v1.z, v1.w);
            uint32_t l01 = pack_bf16x2(v0.x - bflo_f(h01), v0.y - bfhi_f(h01));
            uint32_t l23 = pack_bf16x2(v0.z - bflo_f(h23), v0.w - bfhi_f(h23));
            uint32_t m01 = pack_bf16x2(v1.x - bflo_f(g01), v1.y - bfhi_f(g01));
            uint32_t m23 = pack_bf16x2(v1.z - bflo_f(g23), v1.w - bfhi_f(g23));
            char* ab = smem + OFF_A + (s ^ 1) * A_STG + arow * ASTR + akq * 8;
            *(uint2*)(ab)             = make_uint2(h01, h23);
            *(uint2*)(ab + 32)        = make_uint2(g01, g23);
            *(uint2*)(ab + A_HL)      = make_uint2(l01, l23);
            *(uint2*)(ab + A_HL + 32) = make_uint2(m01, m23);
            CPWAIT0();
        }
        __syncthreads();
    }

    // ---------------- epilogue ----------------
    // alpha: reduce over 4 threads of the row quad
    aacc += __shfl_xor_sync(0xffffffffu, aacc, 1);
    aacc += __shfl_xor_sync(0xffffffffu, aacc, 2);
    if ((lid & 3) == 0) alps[arow] = aacc;

    // rowsum partials: silu + W2 over this thread's cols
    {
        float b1a[4], b1b[4], w2a[4], w2b[4];
        #pragma unroll
        for (int nt = 0; nt < 4; ++nt) {
            int col = wn * 32 + nt * 8 + 2 * (lid & 3);
            b1a[nt] = b1s[col];     b1b[nt] = b1s[col + 1];
            w2a[nt] = w2s[col];     w2b[nt] = w2s[col + 1];
        }
        #pragma unroll
        for (int mt = 0; mt < 4; ++mt) {
            float p0 = 0.0f, p1 = 0.0f;
            #pragma unroll
            for (int nt = 0; nt < 4; ++nt) {
                p0 += silu_f(acc[mt][nt][0] + b1a[nt]) * w2a[nt]
                    + silu_f(acc[mt][nt][1] + b1b[nt]) * w2b[nt];
                p1 += silu_f(acc[mt][nt][2] + b1a[nt]) * w2a[nt]
                    + silu_f(acc[mt][nt][3] + b1b[nt]) * w2b[nt];
            }
            p0 += __shfl_xor_sync(0xffffffffu, p0, 1);
            p0 += __shfl_xor_sync(0xffffffffu, p0, 2);
            p1 += __shfl_xor_sync(0xffffffffu, p1, 1);
            p1 += __shfl_xor_sync(0xffffffffu, p1, 2);
            if ((lid & 3) == 0) {
                int r = wm * 64 + mt * 16 + (lid >> 2);
                atomicAdd(&rsum[r], p0);
                atomicAdd(&rsum[r + 8], p1);
            }
        }
    }
    __syncthreads();

    // final: gate + segment sum (warps 0-3)
    if (tid < 128) {
        const int row = tid, grow = row0 + row;
        const bool valid = grow < N_ROWS;
        const float b2v = __ldg(b2), bwv = __ldg(bw);
        float val = valid ? (rsum[row] + b2v) * (alps[row] + bwv) : 0.0f;
        int g = valid
            ? (is64 ? (int)((const long long*)batch_raw)[grow] : ((const int*)batch_raw)[grow])
            : -1;
        float tot = 0.0f;
        #pragma unroll
        for (int k2 = 0; k2 < 32; ++k2) {
            float vk = __shfl_sync(0xffffffffu, val, k2);
            int   gk = __shfl_sync(0xffffffffu, g, k2);
            if (gk == g) tot += vk;
        }
        int gp = __shfl_up_sync(0xffffffffu, g, 1);
        if (valid && (lid == 0 || g != gp)) atomicAdd(out + g, tot);
    }
}

// ---------------- launch ----------------
extern "C" void kernel_launch(void* const* d_in, const int* in_sizes, int n_in,
                              void* d_out, int out_size) {
    const float* h     = (const float*)d_in[0];
    const void*  batch = d_in[3];
    const float* W1    = (const float*)d_in[5];
    const float* b1    = (const float*)d_in[6];
    const float* W2    = (const float*)d_in[7];
    const float* b2    = (const float*)d_in[8];
    const float* Ww    = (const float*)d_in[9];
    const float* bw    = (const float*)d_in[10];
    float* out = (float*)d_out;

    cudaFuncSetAttribute(fused_mma_kernel,
                         cudaFuncAttributeMaxDynamicSharedMemorySize, SMEM_TOTAL);

    zero_out_kernel<<<(NG + 255) / 256, 256>>>(out);
    convert_w1_kernel<<<(HHALF * HID) / 256, 256>>>(W1);

    int grid = (N_ROWS + MROWS - 1) / MROWS;   // 1563
    fused_mma_kernel<<<grid, NTHREADS, SMEM_TOTAL>>>(h, batch, b1, W2, b2, Ww, bw, out);
}

// round 4
// speedup vs baseline: 3.9539x; 1.1479x over previous
#include <cuda_runtime.h>
#include <cuda_bf16.h>
#include <cstdint>

#define N_ROWS 200000
#define HID    512
#define HHALF  256
#define NG     2000
#define MROWS  128
#define KC     64
#define NCHUNK 8
#define NTHREADS 256

// smem byte offsets
#define OFF_B1    0
#define OFF_W2    1024
#define OFF_ALPHA 2048      // 128*8*4 = 4KB
#define OFF_RSUM  6144      // 512B
#define OFF_A     8192      // 2 stages * 32KB (hi 16KB + lo 16KB)
#define A_STG     32768
#define A_LO      16384
#define OFF_B     73728     // 2 stages * 64KB (hi 32KB + lo 32KB)
#define B_STG     65536
#define B_LO      32768
#define SMEM_TOTAL 204800

__device__ __nv_bfloat16 g_W1hi[HHALF * HID];
__device__ __nv_bfloat16 g_W1lo[HHALF * HID];

// ---------------- helpers ----------------
__device__ __forceinline__ uint32_t smem_u32(const void* p) {
    uint32_t a;
    asm("{ .reg .u64 t; cvta.to.shared.u64 t, %1; cvt.u32.u64 %0, t; }" : "=r"(a) : "l"(p));
    return a;
}
#define LDSM4(r, a) asm volatile("ldmatrix.sync.aligned.m8n8.x4.shared.b16 {%0,%1,%2,%3}, [%4];" \
    : "=r"((r)[0]),"=r"((r)[1]),"=r"((r)[2]),"=r"((r)[3]) : "r"(a))
#define MMA16816(d, a, b0, b1) asm volatile( \
    "mma.sync.aligned.m16n8k16.row.col.f32.bf16.bf16.f32 " \
    "{%0,%1,%2,%3}, {%4,%5,%6,%7}, {%8,%9}, {%0,%1,%2,%3};" \
    : "+f"((d)[0]),"+f"((d)[1]),"+f"((d)[2]),"+f"((d)[3]) \
    : "r"((a)[0]),"r"((a)[1]),"r"((a)[2]),"r"((a)[3]), "r"(b0),"r"(b1))
#define CPASYNC16(dst, src) asm volatile("cp.async.cg.shared.global [%0], [%1], 16;" :: "r"(dst), "l"(src) : "memory")
#define CPCOMMIT() asm volatile("cp.async.commit_group;" ::: "memory")
#define CPWAIT0()  asm volatile("cp.async.wait_group 0;" ::: "memory")

__device__ __forceinline__ uint32_t pack_bf16x2(float e_lo, float e_hi) {
    uint32_t r;
    asm("cvt.rn.bf16x2.f32 %0, %1, %2;" : "=r"(r) : "f"(e_hi), "f"(e_lo));
    return r;
}
__device__ __forceinline__ float bflo_f(uint32_t p) { return __uint_as_float(p << 16); }
__device__ __forceinline__ float bfhi_f(uint32_t p) { return __uint_as_float(p & 0xffff0000u); }
__device__ __forceinline__ float silu_f(float z) { return __fdividef(z, 1.0f + __expf(-z)); }

// ---------------- prep kernel (zero out + split W1) ----------------
__global__ void prep_kernel(const float* __restrict__ W1, float* __restrict__ out) {
    int i = blockIdx.x * blockDim.x + threadIdx.x;
    if (i < NG) out[i] = 0.0f;
    if (i < HHALF * HID) {
        float x = W1[i];
        __nv_bfloat16 hi = __float2bfloat16(x);
        g_W1hi[i] = hi;
        g_W1lo[i] = __float2bfloat16(x - __bfloat162float(hi));
    }
}

// ---------------- device helpers for main kernel ----------------
__device__ __forceinline__ void stage_B(uint32_t sbase, int st, int kk, int tid) {
    #pragma unroll
    for (int j = 0; j < 16; ++j) {
        int task = tid + j * 256;
        int hl   = task >> 11;
        int rem  = task & 2047;
        int n    = rem >> 3;
        int unit = rem & 7;
        const __nv_bfloat16* src = (hl ? g_W1lo : g_W1hi) + n * HID + kk + unit * 8;
        uint32_t dst = sbase + OFF_B + st * B_STG + hl * B_LO + n * 128
                     + (((unsigned)(unit ^ (n & 7))) << 4);
        CPASYNC16(dst, src);
    }
    CPCOMMIT();
}

__device__ __forceinline__ void load_va(float4 va[4][2], const float* __restrict__ h,
                                        int row0, int tid, int kk) {
    const int slot = tid & 7;
    #pragma unroll
    for (int i = 0; i < 4; ++i) {
        int row = (tid >> 3) + i * 32;
        int grow = row0 + row;
        if (grow < N_ROWS) {
            const float* p = h + (size_t)grow * HID + kk + slot * 8;
            va[i][0] = __ldg((const float4*)p);
            va[i][1] = __ldg((const float4*)(p + 4));
        } else {
            va[i][0] = make_float4(0.f, 0.f, 0.f, 0.f);
            va[i][1] = va[i][0];
        }
    }
}

__device__ __forceinline__ void convert_chunk(char* smem, uint32_t abytes,
                                              const float4 va[4][2],
                                              const float* __restrict__ Ww,
                                              int kk, int tid, float* aacc) {
    const int slot = tid & 7;
    float4 wk0 = __ldg((const float4*)(Ww + kk + slot * 8));
    float4 wk1 = __ldg((const float4*)(Ww + kk + slot * 8 + 4));
    #pragma unroll
    for (int i = 0; i < 4; ++i) {
        int row = (tid >> 3) + i * 32;
        float4 v0 = va[i][0], v1 = va[i][1];
        aacc[i] = fmaf(v0.x, wk0.x, fmaf(v0.y, wk0.y, fmaf(v0.z, wk0.z, fmaf(v0.w, wk0.w, aacc[i]))));
        aacc[i] = fmaf(v1.x, wk1.x, fmaf(v1.y, wk1.y, fmaf(v1.z, wk1.z, fmaf(v1.w, wk1.w, aacc[i]))));
        uint32_t h0 = pack_bf16x2(v0.x, v0.y), h1 = pack_bf16x2(v0.z, v0.w);
        uint32_t h2 = pack_bf16x2(v1.x, v1.y), h3 = pack_bf16x2(v1.z, v1.w);
        uint32_t l0 = pack_bf16x2(v0.x - bflo_f(h0), v0.y - bfhi_f(h0));
        uint32_t l1 = pack_bf16x2(v0.z - bflo_f(h1), v0.w - bfhi_f(h1));
        uint32_t l2 = pack_bf16x2(v1.x - bflo_f(h2), v1.y - bfhi_f(h2));
        uint32_t l3 = pack_bf16x2(v1.z - bflo_f(h3), v1.w - bfhi_f(h3));
        uint32_t off = (unsigned)row * 128 + (((unsigned)(slot ^ (row & 7))) << 4);
        *(uint4*)(smem + abytes + off)        = make_uint4(h0, h1, h2, h3);
        *(uint4*)(smem + abytes + A_LO + off) = make_uint4(l0, l1, l2, l3);
    }
}

// ---------------- main kernel ----------------
__global__ __launch_bounds__(NTHREADS, 1)
void fused_mma_kernel(
    const float* __restrict__ h,
    const void*  __restrict__ batch_raw,
    const float* __restrict__ b1,
    const float* __restrict__ W2,
    const float* __restrict__ b2,
    const float* __restrict__ Ww,
    const float* __restrict__ bw,
    float* __restrict__ out)
{
    extern __shared__ char smem[];
    const uint32_t sbase = smem_u32(smem);
    const int tid = threadIdx.x;
    const int wid = tid >> 5, lid = tid & 31;
    const int row0 = blockIdx.x * MROWS;

    float* b1s  = (float*)(smem + OFF_B1);
    float* w2s  = (float*)(smem + OFF_W2);
    float* alps = (float*)(smem + OFF_ALPHA);
    float* rsum = (float*)(smem + OFF_RSUM);

    b1s[tid] = b1[tid];
    w2s[tid] = W2[tid];
    if (tid < 128) rsum[tid] = 0.0f;

    const bool is64 = (((const int*)batch_raw)[N_ROWS - 1] == 0);

    float acc[4][8][4];
    #pragma unroll
    for (int a = 0; a < 4; ++a)
        #pragma unroll
        for (int b = 0; b < 8; ++b)
            #pragma unroll
            for (int c = 0; c < 4; ++c) acc[a][b][c] = 0.0f;

    float aacc[4] = {0.f, 0.f, 0.f, 0.f};
    float4 va[4][2];

    // ---------------- prologue: stage chunk 0 ----------------
    stage_B(sbase, 0, 0, tid);
    load_va(va, h, row0, tid, 0);
    convert_chunk(smem, OFF_A, va, Ww, 0, tid, aacc);
    CPWAIT0();
    __syncthreads();

    // warp layout: 2 x 4 grid of 64x64 tiles
    const int wm = wid >> 2;          // 0..1
    const int wn = wid & 3;           // 0..3
    const int arow_lane = wm * 64 + (lid & 15);
    const int a_uhalf   = lid >> 4;
    const int b_nlane   = wn * 64 + (lid & 7) + ((lid >> 4) << 3);
    const int b_uhalf   = (lid >> 3) & 1;

    // ---------------- main loop ----------------
    for (int c = 0; c < NCHUNK; ++c) {
        const int s = c & 1;
        const bool more = (c + 1) < NCHUNK;
        if (more) {
            stage_B(sbase, s ^ 1, (c + 1) * KC, tid);
            load_va(va, h, row0, tid, (c + 1) * KC);
        }

        const uint32_t abase = sbase + OFF_A + s * A_STG;
        const uint32_t bbase = sbase + OFF_B + s * B_STG;

        #pragma unroll
        for (int ks = 0; ks < 4; ++ks) {
            uint32_t ah[4][4], bh[4][4];
            #pragma unroll
            for (int mt = 0; mt < 4; ++mt) {
                int row = arow_lane + mt * 16;
                uint32_t u = (uint32_t)((ks * 2 + a_uhalf) ^ (row & 7));
                LDSM4(ah[mt], abase + (unsigned)row * 128 + (u << 4));
            }
            #pragma unroll
            for (int p = 0; p < 4; ++p) {
                int n = b_nlane + p * 16;
                uint32_t u = (uint32_t)((ks * 2 + b_uhalf) ^ (n & 7));
                LDSM4(bh[p], bbase + (unsigned)n * 128 + (u << 4));
            }
            #pragma unroll
            for (int mt = 0; mt < 4; ++mt)
                #pragma unroll
                for (int nt = 0; nt < 8; ++nt)
                    MMA16816(acc[mt][nt], ah[mt], bh[nt >> 1][(nt & 1) * 2], bh[nt >> 1][(nt & 1) * 2 + 1]);

            uint32_t bl[4][4];
            #pragma unroll
            for (int p = 0; p < 4; ++p) {
                int n = b_nlane + p * 16;
                uint32_t u = (uint32_t)((ks * 2 + b_uhalf) ^ (n & 7));
                LDSM4(bl[p], bbase + B_LO + (unsigned)n * 128 + (u << 4));
            }
            #pragma unroll
            for (int mt = 0; mt < 4; ++mt)
                #pragma unroll
                for (int nt = 0; nt < 8; ++nt)
                    MMA16816(acc[mt][nt], ah[mt], bl[nt >> 1][(nt & 1) * 2], bl[nt >> 1][(nt & 1) * 2 + 1]);

            uint32_t al[4][4];
            #pragma unroll
            for (int mt = 0; mt < 4; ++mt) {
                int row = arow_lane + mt * 16;
                uint32_t u = (uint32_t)((ks * 2 + a_uhalf) ^ (row & 7));
                LDSM4(al[mt], abase + A_LO + (unsigned)row * 128 + (u << 4));
            }
            #pragma unroll
            for (int mt = 0; mt < 4; ++mt)
                #pragma unroll
                for (int nt = 0; nt < 8; ++nt)
                    MMA16816(acc[mt][nt], al[mt], bh[nt >> 1][(nt & 1) * 2], bh[nt >> 1][(nt & 1) * 2 + 1]);
        }

        if (more) {
            convert_chunk(smem, OFF_A + (s ^ 1) * A_STG, va, Ww, (c + 1) * KC, tid, aacc);
            CPWAIT0();
        }
        __syncthreads();
    }

    // ---------------- epilogue ----------------
    // alpha partials -> smem
    {
        const int slot = tid & 7;
        #pragma unroll
        for (int i = 0; i < 4; ++i) {
            int row = (tid >> 3) + i * 32;
            alps[row * 8 + slot] = aacc[i];
        }
    }

    // rowsum partials: silu + W2 over this warp's 64 cols
    {
        #pragma unroll
        for (int mt = 0; mt < 4; ++mt) {
            float p0 = 0.0f, p1 = 0.0f;
            #pragma unroll
            for (int nt = 0; nt < 8; ++nt) {
                int col = wn * 64 + nt * 8 + 2 * (lid & 3);
                float bA = b1s[col], bB = b1s[col + 1];
                float wA = w2s[col], wB = w2s[col + 1];
                p0 += silu_f(acc[mt][nt][0] + bA) * wA + silu_f(acc[mt][nt][1] + bB) * wB;
                p1 += silu_f(acc[mt][nt][2] + bA) * wA + silu_f(acc[mt][nt][3] + bB) * wB;
            }
            p0 += __shfl_xor_sync(0xffffffffu, p0, 1);
            p0 += __shfl_xor_sync(0xffffffffu, p0, 2);
            p1 += __shfl_xor_sync(0xffffffffu, p1, 1);
            p1 += __shfl_xor_sync(0xffffffffu, p1, 2);
            if ((lid & 3) == 0) {
                int r = wm * 64 + mt * 16 + (lid >> 2);
                atomicAdd(&rsum[r], p0);
                atomicAdd(&rsum[r + 8], p1);
            }
        }
    }
    __syncthreads();

    // final: gate + segment sum (warps 0-3)
    if (tid < 128) {
        const int row = tid, grow = row0 + row;
        const bool valid = grow < N_ROWS;
        float alr = 0.0f;
        #pragma unroll
        for (int s2 = 0; s2 < 8; ++s2) alr += alps[row * 8 + s2];
        const float b2v = __ldg(b2), bwv = __ldg(bw);
        float val = valid ? (rsum[row] + b2v) * (alr + bwv) : 0.0f;
        int g = valid
            ? (is64 ? (int)((const long long*)batch_raw)[grow] : ((const int*)batch_raw)[grow])
            : -1;
        float tot = 0.0f;
        #pragma unroll
        for (int k2 = 0; k2 < 32; ++k2) {
            float vk = __shfl_sync(0xffffffffu, val, k2);
            int   gk = __shfl_sync(0xffffffffu, g, k2);
            if (gk == g) tot += vk;
        }
        int gp = __shfl_up_sync(0xffffffffu, g, 1);
        if (valid && (lid == 0 || g != gp)) atomicAdd(out + g, tot);
    }
}

// ---------------- launch ----------------
extern "C" void kernel_launch(void* const* d_in, const int* in_sizes, int n_in,
                              void* d_out, int out_size) {
    const float* h     = (const float*)d_in[0];
    const void*  batch = d_in[3];
    const float* W1    = (const float*)d_in[5];
    const float* b1    = (const float*)d_in[6];
    const float* W2    = (const float*)d_in[7];
    const float* b2    = (const float*)d_in[8];
    const float* Ww    = (const float*)d_in[9];
    const float* bw    = (const float*)d_in[10];
    float* out = (float*)d_out;

    cudaFuncSetAttribute(fused_mma_kernel,
                         cudaFuncAttributeMaxDynamicSharedMemorySize, SMEM_TOTAL);

    prep_kernel<<<(HHALF * HID) / 256, 256>>>(W1, out);

    int grid = (N_ROWS + MROWS - 1) / MROWS;   // 1563
    fused_mma_kernel<<<grid, NTHREADS, SMEM_TOTAL>>>(h, batch, b1, W2, b2, Ww, bw, out);
}